// round 14
// baseline (speedup 1.0000x reference)
#include <cuda_runtime.h>
#include <cuda_fp16.h>

#define NN    50000
#define EEMAX 1600000
#define ETOT  (EEMAX + NN)
#define HID   32

// ---- static scratch (module zero-init; g_deg kept zero as an invariant) ----
__device__ int    g_deg[NN];
__device__ int    g_roff[NN + 1];
__device__ int    g_cur[NN];
__device__ int    g_rank[EEMAX];
__device__ int    g_csr[ETOT];
__device__ int    g_part[64];   // lookback flags: 0 = unpublished, else total+1
// bank 1: layer-1 features/scores   bank 2: layer-2 (written by aggA)
// 128B alignment -> every 128B row is exactly one cache line
__device__ __align__(128) __half2 g_lin[NN * HID];
__device__ __align__(128) __half2 g_lin2[NN * HID];
__device__ __align__(8)  float2 g_es[NN];
__device__ __align__(8)  float2 g_es2[NN];
__device__ __align__(8)  float2 g_ed[NN];
__device__ __align__(8)  float2 g_ed2[NN];

// ---------------- fused front: lin1 blocks + hist blocks ----------------
__global__ void __launch_bounds__(256) k_front(
    const float* __restrict__ x,
    const float* __restrict__ Wc, const float* __restrict__ asc_, const float* __restrict__ adc,
    const float* __restrict__ Wr, const float* __restrict__ asr_, const float* __restrict__ adr,
    const int* __restrict__ dst, int E, int n, int nb_lin) {
    if (blockIdx.x >= (unsigned)nb_lin) {
        // ---- histogram + rank path (keeps atomic return = rank) ----
        int hb = blockIdx.x - nb_lin;
        int base = (hb * blockDim.x + threadIdx.x) * 8;
        if (base + 7 < E) {
            int4 a = *(const int4*)(dst + base);
            int4 b = *(const int4*)(dst + base + 4);
            int d[8] = {a.x, a.y, a.z, a.w, b.x, b.y, b.z, b.w};
            int rk[8];
            #pragma unroll
            for (int k = 0; k < 8; k++) {
                bool ok = (unsigned)d[k] < (unsigned)n;
                rk[k] = ok ? atomicAdd(&g_deg[d[k]], 1) : -1;
            }
            *(int4*)(g_rank + base)     = make_int4(rk[0], rk[1], rk[2], rk[3]);
            *(int4*)(g_rank + base + 4) = make_int4(rk[4], rk[5], rk[6], rk[7]);
        } else {
            for (int k = base; k < E; k++) {
                int dv = dst[k];
                g_rank[k] = ((unsigned)dv < (unsigned)n)
                            ? atomicAdd(&g_deg[dv], 1) : -1;
            }
        }
        return;
    }
    // ---- lin1 path ----
    __shared__ float Wsc[64 * HID], Wsr[64 * HID];
    __shared__ float av[4 * HID];
    for (int i = threadIdx.x; i < 64 * HID; i += blockDim.x) {
        Wsc[i] = Wc[i]; Wsr[i] = Wr[i];
    }
    if (threadIdx.x < HID) {
        av[threadIdx.x]           = asc_[threadIdx.x];
        av[HID + threadIdx.x]     = adc[threadIdx.x];
        av[2 * HID + threadIdx.x] = asr_[threadIdx.x];
        av[3 * HID + threadIdx.x] = adr[threadIdx.x];
    }
    __syncthreads();
    int gw = (blockIdx.x * blockDim.x + threadIdx.x) >> 5;
    int lane = threadIdx.x & 31;
    if (gw >= n) return;
    const float* xr = x + (size_t)gw * 64;
    float ac = 0.f, ar = 0.f;
    #pragma unroll
    for (int k = 0; k < 64; k++) {
        float xv = xr[k];
        ac = fmaf(xv, Wsc[k * HID + lane], ac);
        ar = fmaf(xv, Wsr[k * HID + lane], ar);
    }
    g_lin[(size_t)gw * HID + lane] = __floats2half2_rn(ac, ar);
    float e0 = ac * av[lane], e1 = ac * av[HID + lane];
    float e2 = ar * av[2 * HID + lane], e3 = ar * av[3 * HID + lane];
    #pragma unroll
    for (int o = 16; o; o >>= 1) {
        e0 += __shfl_xor_sync(0xffffffffu, e0, o);
        e1 += __shfl_xor_sync(0xffffffffu, e1, o);
        e2 += __shfl_xor_sync(0xffffffffu, e2, o);
        e3 += __shfl_xor_sync(0xffffffffu, e3, o);
    }
    if (lane == 0) {
        g_es[gw] = make_float2(e0, e2);
        g_ed[gw] = make_float2(e1, e3);
    }
}

__global__ void k_hist64(const long long* __restrict__ dst, int E, int n) {
    int e = blockIdx.x * blockDim.x + threadIdx.x;
    if (e < E) {
        int d = (int)dst[e];
        if ((unsigned)d < (unsigned)n) atomicAdd(&g_deg[d], 1);
    }
}

__device__ __forceinline__ int warp_incl_scan(int x, int lane) {
    #pragma unroll
    for (int o = 1; o < 32; o <<= 1) {
        int y = __shfl_up_sync(0xffffffffu, x, o);
        if (lane >= o) x += y;
    }
    return x;
}

// ---- single-kernel decoupled-lookback scan ----
__global__ void kb_scan_lb(int nbp, int n) {
    __shared__ int wsum[32];
    __shared__ int s_prev;
    int tid = threadIdx.x, lane = tid & 31, wid = tid >> 5;
    int i = blockIdx.x * 1024 + tid;
    int v = 0;
    if (i < n) { v = g_deg[i] + 1; g_deg[i] = 0; }   // +1 = self loop
    int x = warp_incl_scan(v, lane);
    if (lane == 31) wsum[wid] = x;
    __syncthreads();
    if (wid == 0) wsum[lane] = warp_incl_scan(wsum[lane], lane);
    __syncthreads();
    int incl = x + (wid ? wsum[wid - 1] : 0);
    int blk_total = wsum[31];
    if (tid == 0)
        ((volatile int*)g_part)[blockIdx.x] = blk_total + 1;   // publish
    if (wid == 0) {
        int sum = 0;
        for (int j = lane; j < blockIdx.x; j += 32) {
            int fv;
            do { fv = ((volatile int*)g_part)[j]; } while (fv == 0);
            sum += fv - 1;
        }
        #pragma unroll
        for (int o = 16; o; o >>= 1) sum += __shfl_xor_sync(0xffffffffu, sum, o);
        if (lane == 0) s_prev = sum;
    }
    __syncthreads();
    int off = s_prev;
    if (i < n) {
        int r = incl - v + off;
        g_roff[i] = r;
        g_csr[r]  = i;        // self loop in first slot
        g_cur[i]  = r + 1;    // (used by int64 fallback scatter only)
    }
    if (blockIdx.x == (unsigned)(nbp - 1) && i == n - 1)
        g_roff[n] = incl + off;
}

// atomic-free scatter: pos = roff[d] + 1 + rank (rank from hist pass)
__global__ void k_scatter8(const int* __restrict__ src,
                           const int* __restrict__ dst, int E, int n) {
    int base = (blockIdx.x * blockDim.x + threadIdx.x) * 8;
    if (base + 7 < E) {
        int4 sa = *(const int4*)(src + base);
        int4 sb = *(const int4*)(src + base + 4);
        int4 da = *(const int4*)(dst + base);
        int4 db = *(const int4*)(dst + base + 4);
        int4 ra = *(const int4*)(g_rank + base);
        int4 rb = *(const int4*)(g_rank + base + 4);
        int s[8] = {sa.x, sa.y, sa.z, sa.w, sb.x, sb.y, sb.z, sb.w};
        int d[8] = {da.x, da.y, da.z, da.w, db.x, db.y, db.z, db.w};
        int rk[8] = {ra.x, ra.y, ra.z, ra.w, rb.x, rb.y, rb.z, rb.w};
        int pos[8];
        #pragma unroll
        for (int k = 0; k < 8; k++)
            pos[k] = (rk[k] >= 0) ? (g_roff[d[k]] + 1 + rk[k]) : -1;
        #pragma unroll
        for (int k = 0; k < 8; k++)
            if (pos[k] >= 0) g_csr[pos[k]] = s[k];
    } else {
        for (int k = base; k < E; k++) {
            int rk = g_rank[k];
            if (rk >= 0) {
                int s = src[k], d = dst[k];
                if ((unsigned)s < (unsigned)n)
                    g_csr[g_roff[d] + 1 + rk] = s;
            }
        }
    }
}

__global__ void k_scatter64(const long long* __restrict__ src,
                            const long long* __restrict__ dst, int E, int n) {
    int e = blockIdx.x * blockDim.x + threadIdx.x;
    if (e >= E) return;
    int s = (int)src[e], d = (int)dst[e];
    if ((unsigned)s >= (unsigned)n || (unsigned)d >= (unsigned)n) return;
    int pos = atomicAdd(&g_cur[d], 1);
    g_csr[pos] = s;
}

// int64 fallback lin1 (separate, unfused)
__global__ void __launch_bounds__(256) k_lin1_only(
    const float* __restrict__ x,
    const float* __restrict__ Wc, const float* __restrict__ asc_, const float* __restrict__ adc,
    const float* __restrict__ Wr, const float* __restrict__ asr_, const float* __restrict__ adr,
    int n) {
    __shared__ float Wsc[64 * HID], Wsr[64 * HID];
    __shared__ float av[4 * HID];
    for (int i = threadIdx.x; i < 64 * HID; i += blockDim.x) {
        Wsc[i] = Wc[i]; Wsr[i] = Wr[i];
    }
    if (threadIdx.x < HID) {
        av[threadIdx.x]           = asc_[threadIdx.x];
        av[HID + threadIdx.x]     = adc[threadIdx.x];
        av[2 * HID + threadIdx.x] = asr_[threadIdx.x];
        av[3 * HID + threadIdx.x] = adr[threadIdx.x];
    }
    __syncthreads();
    int gw = (blockIdx.x * blockDim.x + threadIdx.x) >> 5;
    int lane = threadIdx.x & 31;
    if (gw >= n) return;
    const float* xr = x + (size_t)gw * 64;
    float ac = 0.f, ar = 0.f;
    #pragma unroll
    for (int k = 0; k < 64; k++) {
        float xv = xr[k];
        ac = fmaf(xv, Wsc[k * HID + lane], ac);
        ar = fmaf(xv, Wsr[k * HID + lane], ar);
    }
    g_lin[(size_t)gw * HID + lane] = __floats2half2_rn(ac, ar);
    float e0 = ac * av[lane], e1 = ac * av[HID + lane];
    float e2 = ar * av[2 * HID + lane], e3 = ar * av[3 * HID + lane];
    #pragma unroll
    for (int o = 16; o; o >>= 1) {
        e0 += __shfl_xor_sync(0xffffffffu, e0, o);
        e1 += __shfl_xor_sync(0xffffffffu, e1, o);
        e2 += __shfl_xor_sync(0xffffffffu, e2, o);
        e3 += __shfl_xor_sync(0xffffffffu, e3, o);
    }
    if (lane == 0) {
        g_es[gw] = make_float2(e0, e2);
        g_ed[gw] = make_float2(e1, e3);
    }
}

// ---------- core single-pass agg, sector-contiguous row loads ----------
// Lane (cg = lane&3) loads u0 = row bytes [cg*16, cg*16+16) and
// u1 = [64+cg*16, +16): each LDG touches 2 full sectors/row (was 4 half-used)
// -> half the L1 wavefronts. Channel ownership: lane cg holds channels
// {cg*4..cg*4+3} (accX[0..3]) and {16+cg*4..+3} (accX[4..7]).
__device__ __forceinline__ void agg_core(const __half2* __restrict__ lin,
                                         const float2* __restrict__ es,
                                         const float2* __restrict__ edv,
                                         int gw, int lane,
                                         float* accc, float* accr,
                                         float& invc, float& invr) {
    int beg = g_roff[gw], end = g_roff[gw + 1];
    float2 ed = edv[gw];
    int eidx = lane >> 2;
    int cg   = lane & 3;
    float sc = 0.f, sr = 0.f;
    #pragma unroll
    for (int j = 0; j < 8; j++) { accc[j] = 0.f; accr[j] = 0.f; }

    // prefetch first chunk's csr
    int i0 = beg + lane;
    int s_next = (i0 < end) ? g_csr[i0] : 0;

    for (int base = beg; base < end; base += 32) {
        int s_l = s_next;
        float2 e = es[s_l];
        int inext = base + 32 + lane;
        int s_n2 = 0;
        if (inext < end) s_n2 = g_csr[inext];
        float wc = 0.f, wr = 0.f;
        if (base + lane < end) {
            float ac_ = e.x + ed.x; ac_ = (ac_ > 0.f) ? ac_ : 0.2f * ac_;
            float ar_ = e.y + ed.y; ar_ = (ar_ > 0.f) ? ar_ : 0.2f * ar_;
            wc = __expf(ac_); wr = __expf(ar_);
        }
        sc += wc; sr += wr;

        #pragma unroll
        for (int j = 0; j < 4; j++) {
            if (base + j * 8 >= end) break;             // warp-uniform
            int lsrc = j * 8 + eidx;
            float wcx = __shfl_sync(0xffffffffu, wc, lsrc);
            float wrx = __shfl_sync(0xffffffffu, wr, lsrc);
            int   s   = __shfl_sync(0xffffffffu, s_l, lsrc);
            const char* rowb = (const char*)(lin + (size_t)s * HID);
            const uint4 u0 = *(const uint4*)(rowb + cg * 16);        // ch cg*4..+3
            const uint4 u1 = *(const uint4*)(rowb + 64 + cg * 16);   // ch 16+cg*4..+3
            float2 f0 = __half22float2(*(const __half2*)&u0.x);
            float2 f1 = __half22float2(*(const __half2*)&u0.y);
            float2 f2 = __half22float2(*(const __half2*)&u0.z);
            float2 f3 = __half22float2(*(const __half2*)&u0.w);
            float2 f4 = __half22float2(*(const __half2*)&u1.x);
            float2 f5 = __half22float2(*(const __half2*)&u1.y);
            float2 f6 = __half22float2(*(const __half2*)&u1.z);
            float2 f7 = __half22float2(*(const __half2*)&u1.w);
            accc[0] = fmaf(wcx, f0.x, accc[0]); accr[0] = fmaf(wrx, f0.y, accr[0]);
            accc[1] = fmaf(wcx, f1.x, accc[1]); accr[1] = fmaf(wrx, f1.y, accr[1]);
            accc[2] = fmaf(wcx, f2.x, accc[2]); accr[2] = fmaf(wrx, f2.y, accr[2]);
            accc[3] = fmaf(wcx, f3.x, accc[3]); accr[3] = fmaf(wrx, f3.y, accr[3]);
            accc[4] = fmaf(wcx, f4.x, accc[4]); accr[4] = fmaf(wrx, f4.y, accr[4]);
            accc[5] = fmaf(wcx, f5.x, accc[5]); accr[5] = fmaf(wrx, f5.y, accr[5]);
            accc[6] = fmaf(wcx, f6.x, accc[6]); accr[6] = fmaf(wrx, f6.y, accr[6]);
            accc[7] = fmaf(wcx, f7.x, accc[7]); accr[7] = fmaf(wrx, f7.y, accr[7]);
        }
        s_next = s_n2;
    }
    #pragma unroll
    for (int o = 16; o; o >>= 1) {
        sc += __shfl_xor_sync(0xffffffffu, sc, o);
        sr += __shfl_xor_sync(0xffffffffu, sr, o);
    }
    invc = 1.0f / sc; invr = 1.0f / sr;
    #pragma unroll
    for (int o = 4; o <= 16; o <<= 1) {
        #pragma unroll
        for (int j = 0; j < 8; j++) {
            accc[j] += __shfl_xor_sync(0xffffffffu, accc[j], o);
            accr[j] += __shfl_xor_sync(0xffffffffu, accr[j], o);
        }
    }
}

// channel-k ownership helpers for the new layout
#define CH_LANE(k)  (((k) < 16) ? ((k) >> 2) : (((k) - 16) >> 2))
#define CH_REG(k)   (((k) < 16) ? ((k) & 3) : (4 + ((k) & 3)))
#define CH_OF(cg,j) (((j) < 4) ? ((cg) * 4 + (j)) : (16 + (cg) * 4 + (j) - 4))

// ---- aggA: layer-1 agg + ReLU + layer-2 linear + layer-2 att coeffs ----
__global__ void __launch_bounds__(256) k_aggA(
    const float* __restrict__ b1c, const float* __restrict__ b1r,
    const float* __restrict__ W2c, const float* __restrict__ as2c, const float* __restrict__ ad2c,
    const float* __restrict__ W2r, const float* __restrict__ as2r, const float* __restrict__ ad2r,
    int n) {
    __shared__ float Wsc[HID * HID], Wsr[HID * HID];
    __shared__ float bsh[2 * HID];
    __shared__ float av[4 * HID];
    for (int i = threadIdx.x; i < HID * HID; i += blockDim.x) {
        Wsc[i] = W2c[i]; Wsr[i] = W2r[i];
    }
    if (threadIdx.x < HID) {
        bsh[threadIdx.x]          = b1c[threadIdx.x];
        bsh[HID + threadIdx.x]    = b1r[threadIdx.x];
        av[threadIdx.x]           = as2c[threadIdx.x];
        av[HID + threadIdx.x]     = ad2c[threadIdx.x];
        av[2 * HID + threadIdx.x] = as2r[threadIdx.x];
        av[3 * HID + threadIdx.x] = ad2r[threadIdx.x];
    }
    __syncthreads();
    int gw = (blockIdx.x * blockDim.x + threadIdx.x) >> 5;
    int lane = threadIdx.x & 31;
    if (gw >= n) return;
    int cg = lane & 3;

    float accc[8], accr[8], invc, invr;
    agg_core(g_lin, g_es, g_ed, gw, lane, accc, accr, invc, invr);

    float hc[8], hr[8];
    #pragma unroll
    for (int j = 0; j < 8; j++) {
        int ch = CH_OF(cg, j);
        hc[j] = fmaxf(fmaf(accc[j], invc, bsh[ch]), 0.f);
        hr[j] = fmaxf(fmaf(accr[j], invr, bsh[HID + ch]), 0.f);
    }
    // layer-2 linear: channel k lives on lane CH_LANE(k), register CH_REG(k)
    float ac = 0.f, ar = 0.f;
    #pragma unroll
    for (int k = 0; k < HID; k++) {
        float tc = __shfl_sync(0xffffffffu, hc[CH_REG(k)], CH_LANE(k));
        float tr = __shfl_sync(0xffffffffu, hr[CH_REG(k)], CH_LANE(k));
        ac = fmaf(tc, Wsc[k * HID + lane], ac);
        ar = fmaf(tr, Wsr[k * HID + lane], ar);
    }
    g_lin2[(size_t)gw * HID + lane] = __floats2half2_rn(ac, ar);
    float e0 = ac * av[lane], e1 = ac * av[HID + lane];
    float e2 = ar * av[2 * HID + lane], e3 = ar * av[3 * HID + lane];
    #pragma unroll
    for (int o = 16; o; o >>= 1) {
        e0 += __shfl_xor_sync(0xffffffffu, e0, o);
        e1 += __shfl_xor_sync(0xffffffffu, e1, o);
        e2 += __shfl_xor_sync(0xffffffffu, e2, o);
        e3 += __shfl_xor_sync(0xffffffffu, e3, o);
    }
    if (lane == 0) {
        g_es2[gw] = make_float2(e0, e2);
        g_ed2[gw] = make_float2(e1, e3);
    }
}

// ---- aggB: layer-2 agg + ReLU + head GEMMs + sigmoid(c) -> d_out ----
__global__ void __launch_bounds__(256) k_aggB(
    const float* __restrict__ b2c, const float* __restrict__ b2r,
    const float* __restrict__ lWc, const float* __restrict__ lbc,
    const float* __restrict__ lWr, const float* __restrict__ lbr,
    float* __restrict__ out, int n) {
    __shared__ float Wsc[HID * HID], Wsr[HID * HID];
    __shared__ float bsh[2 * HID];
    __shared__ float lbsh[2 * HID];
    for (int i = threadIdx.x; i < HID * HID; i += blockDim.x) {
        Wsc[i] = lWc[i]; Wsr[i] = lWr[i];
    }
    if (threadIdx.x < HID) {
        bsh[threadIdx.x]        = b2c[threadIdx.x];
        bsh[HID + threadIdx.x]  = b2r[threadIdx.x];
        lbsh[threadIdx.x]       = lbc[threadIdx.x];
        lbsh[HID + threadIdx.x] = lbr[threadIdx.x];
    }
    __syncthreads();
    int gw = (blockIdx.x * blockDim.x + threadIdx.x) >> 5;
    int lane = threadIdx.x & 31;
    if (gw >= n) return;
    int cg = lane & 3;

    float accc[8], accr[8], invc, invr;
    agg_core(g_lin2, g_es2, g_ed2, gw, lane, accc, accr, invc, invr);

    float hc[8], hr[8];
    #pragma unroll
    for (int j = 0; j < 8; j++) {
        int ch = CH_OF(cg, j);
        hc[j] = fmaxf(fmaf(accc[j], invc, bsh[ch]), 0.f);
        hr[j] = fmaxf(fmaf(accr[j], invr, bsh[HID + ch]), 0.f);
    }
    float ac = lbsh[lane], ar = lbsh[HID + lane];
    #pragma unroll
    for (int k = 0; k < HID; k++) {
        float tc = __shfl_sync(0xffffffffu, hc[CH_REG(k)], CH_LANE(k));
        float tr = __shfl_sync(0xffffffffu, hr[CH_REG(k)], CH_LANE(k));
        ac = fmaf(tc, Wsc[k * HID + lane], ac);
        ar = fmaf(tr, Wsr[k * HID + lane], ar);
    }
    out[(size_t)gw * HID + lane] = 1.0f / (1.0f + __expf(-ac));
    out[(size_t)n * HID + (size_t)gw * HID + lane] = ar;
}

// ---------------- launch ----------------
extern "C" void kernel_launch(void* const* d_in, const int* in_sizes, int n_in,
                              void* d_out, int out_size) {
    const float* x = (const float*)d_in[0];
    int n = in_sizes[0] / 64;

    // params: c at d_in[2..11], r at d_in[12..21]
    const float** c = (const float**)(d_in + 2);
    const float** r = (const float**)(d_in + 12);

    const int T = 256;
    long long nelem = in_sizes[1];
    int nb_scan = (n + 1023) / 1024;
    int nb = (n * 32 + T - 1) / T;  // warp per node

    if (nelem == 2LL * EEMAX) {            // int32 [2, E]
        const int* ei = (const int*)d_in[1];
        int E = EEMAX;
        int nt8 = (E + 7) / 8;
        int nb_hist = (nt8 + T - 1) / T;
        k_front<<<nb + nb_hist, T>>>(x, c[0], c[1], c[2], r[0], r[1], r[2],
                                     ei + E, E, n, nb);
        kb_scan_lb<<<nb_scan, 1024>>>(nb_scan, n);
        k_scatter8<<<nb_hist, T>>>(ei, ei + E, E, n);
    } else {                               // int64 [2, E] fallback
        const long long* ei = (const long long*)d_in[1];
        int E = (int)(nelem / 2);
        k_lin1_only<<<nb, T>>>(x, c[0], c[1], c[2], r[0], r[1], r[2], n);
        k_hist64<<<(E + T - 1) / T, T>>>(ei + E, E, n);
        kb_scan_lb<<<nb_scan, 1024>>>(nb_scan, n);
        k_scatter64<<<(E + T - 1) / T, T>>>(ei, ei + E, E, n);
    }

    k_aggA<<<nb, T>>>(c[3], r[3], c[4], c[5], c[6], r[4], r[5], r[6], n);
    k_aggB<<<nb, T>>>(c[7], r[7], c[8], c[9], r[8], r[9], (float*)d_out, n);
}

// round 15
// speedup vs baseline: 1.0925x; 1.0925x over previous
#include <cuda_runtime.h>
#include <cuda_fp16.h>

#define NN    50000
#define EEMAX 1600000
#define ETOT  (EEMAX + NN)
#define HID   32

// ---- static scratch (module zero-init; g_deg kept zero as an invariant) ----
__device__ int    g_deg[NN];
__device__ int    g_roff[NN + 1];
__device__ int    g_cur[NN];
__device__ int    g_rank[EEMAX];
__device__ int    g_csr[ETOT];
__device__ int    g_part[64];   // lookback flags: 0 = unpublished, else total+1
// bank 1: layer-1 features/scores   bank 2: layer-2 (written by aggA)
__device__ __align__(128) __half2 g_lin[NN * HID];
__device__ __align__(128) __half2 g_lin2[NN * HID];
__device__ __align__(8)  float2 g_es[NN];
__device__ __align__(8)  float2 g_es2[NN];
__device__ __align__(8)  float2 g_ed[NN];
__device__ __align__(8)  float2 g_ed2[NN];

// ---------------- fused front: lin1 blocks + hist blocks ----------------
__global__ void __launch_bounds__(256) k_front(
    const float* __restrict__ x,
    const float* __restrict__ Wc, const float* __restrict__ asc_, const float* __restrict__ adc,
    const float* __restrict__ Wr, const float* __restrict__ asr_, const float* __restrict__ adr,
    const int* __restrict__ dst, int E, int n, int nb_lin) {
    if (blockIdx.x >= (unsigned)nb_lin) {
        // ---- histogram + rank path (keeps atomic return = rank) ----
        int hb = blockIdx.x - nb_lin;
        int base = (hb * blockDim.x + threadIdx.x) * 8;
        if (base + 7 < E) {
            int4 a = *(const int4*)(dst + base);
            int4 b = *(const int4*)(dst + base + 4);
            int d[8] = {a.x, a.y, a.z, a.w, b.x, b.y, b.z, b.w};
            int rk[8];
            #pragma unroll
            for (int k = 0; k < 8; k++) {
                bool ok = (unsigned)d[k] < (unsigned)n;
                rk[k] = ok ? atomicAdd(&g_deg[d[k]], 1) : -1;
            }
            *(int4*)(g_rank + base)     = make_int4(rk[0], rk[1], rk[2], rk[3]);
            *(int4*)(g_rank + base + 4) = make_int4(rk[4], rk[5], rk[6], rk[7]);
        } else {
            for (int k = base; k < E; k++) {
                int dv = dst[k];
                g_rank[k] = ((unsigned)dv < (unsigned)n)
                            ? atomicAdd(&g_deg[dv], 1) : -1;
            }
        }
        return;
    }
    // ---- lin1 path ----
    __shared__ float Wsc[64 * HID], Wsr[64 * HID];
    __shared__ float av[4 * HID];
    for (int i = threadIdx.x; i < 64 * HID; i += blockDim.x) {
        Wsc[i] = Wc[i]; Wsr[i] = Wr[i];
    }
    if (threadIdx.x < HID) {
        av[threadIdx.x]           = asc_[threadIdx.x];
        av[HID + threadIdx.x]     = adc[threadIdx.x];
        av[2 * HID + threadIdx.x] = asr_[threadIdx.x];
        av[3 * HID + threadIdx.x] = adr[threadIdx.x];
    }
    __syncthreads();
    int gw = (blockIdx.x * blockDim.x + threadIdx.x) >> 5;
    int lane = threadIdx.x & 31;
    if (gw >= n) return;
    const float* xr = x + (size_t)gw * 64;
    float ac = 0.f, ar = 0.f;
    #pragma unroll
    for (int k = 0; k < 64; k++) {
        float xv = xr[k];
        ac = fmaf(xv, Wsc[k * HID + lane], ac);
        ar = fmaf(xv, Wsr[k * HID + lane], ar);
    }
    g_lin[(size_t)gw * HID + lane] = __floats2half2_rn(ac, ar);
    float e0 = ac * av[lane], e1 = ac * av[HID + lane];
    float e2 = ar * av[2 * HID + lane], e3 = ar * av[3 * HID + lane];
    #pragma unroll
    for (int o = 16; o; o >>= 1) {
        e0 += __shfl_xor_sync(0xffffffffu, e0, o);
        e1 += __shfl_xor_sync(0xffffffffu, e1, o);
        e2 += __shfl_xor_sync(0xffffffffu, e2, o);
        e3 += __shfl_xor_sync(0xffffffffu, e3, o);
    }
    if (lane == 0) {
        g_es[gw] = make_float2(e0, e2);
        g_ed[gw] = make_float2(e1, e3);
    }
}

__global__ void k_hist64(const long long* __restrict__ dst, int E, int n) {
    int e = blockIdx.x * blockDim.x + threadIdx.x;
    if (e < E) {
        int d = (int)dst[e];
        if ((unsigned)d < (unsigned)n) atomicAdd(&g_deg[d], 1);
    }
}

__device__ __forceinline__ int warp_incl_scan(int x, int lane) {
    #pragma unroll
    for (int o = 1; o < 32; o <<= 1) {
        int y = __shfl_up_sync(0xffffffffu, x, o);
        if (lane >= o) x += y;
    }
    return x;
}

// ---- single-kernel decoupled-lookback scan ----
__global__ void kb_scan_lb(int nbp, int n) {
    __shared__ int wsum[32];
    __shared__ int s_prev;
    int tid = threadIdx.x, lane = tid & 31, wid = tid >> 5;
    int i = blockIdx.x * 1024 + tid;
    int v = 0;
    if (i < n) { v = g_deg[i] + 1; g_deg[i] = 0; }   // +1 = self loop
    int x = warp_incl_scan(v, lane);
    if (lane == 31) wsum[wid] = x;
    __syncthreads();
    if (wid == 0) wsum[lane] = warp_incl_scan(wsum[lane], lane);
    __syncthreads();
    int incl = x + (wid ? wsum[wid - 1] : 0);
    int blk_total = wsum[31];
    if (tid == 0)
        ((volatile int*)g_part)[blockIdx.x] = blk_total + 1;   // publish
    if (wid == 0) {
        int sum = 0;
        for (int j = lane; j < blockIdx.x; j += 32) {
            int fv;
            do { fv = ((volatile int*)g_part)[j]; } while (fv == 0);
            sum += fv - 1;
        }
        #pragma unroll
        for (int o = 16; o; o >>= 1) sum += __shfl_xor_sync(0xffffffffu, sum, o);
        if (lane == 0) s_prev = sum;
    }
    __syncthreads();
    int off = s_prev;
    if (i < n) {
        int r = incl - v + off;
        g_roff[i] = r;
        g_csr[r]  = i;        // self loop in first slot
        g_cur[i]  = r + 1;    // (used by int64 fallback scatter only)
    }
    if (blockIdx.x == (unsigned)(nbp - 1) && i == n - 1)
        g_roff[n] = incl + off;
}

// atomic-free scatter: pos = roff[d] + 1 + rank (rank from hist pass)
__global__ void k_scatter8(const int* __restrict__ src,
                           const int* __restrict__ dst, int E, int n) {
    int base = (blockIdx.x * blockDim.x + threadIdx.x) * 8;
    if (base + 7 < E) {
        int4 sa = *(const int4*)(src + base);
        int4 sb = *(const int4*)(src + base + 4);
        int4 da = *(const int4*)(dst + base);
        int4 db = *(const int4*)(dst + base + 4);
        int4 ra = *(const int4*)(g_rank + base);
        int4 rb = *(const int4*)(g_rank + base + 4);
        int s[8] = {sa.x, sa.y, sa.z, sa.w, sb.x, sb.y, sb.z, sb.w};
        int d[8] = {da.x, da.y, da.z, da.w, db.x, db.y, db.z, db.w};
        int rk[8] = {ra.x, ra.y, ra.z, ra.w, rb.x, rb.y, rb.z, rb.w};
        int pos[8];
        #pragma unroll
        for (int k = 0; k < 8; k++)
            pos[k] = (rk[k] >= 0) ? (g_roff[d[k]] + 1 + rk[k]) : -1;
        #pragma unroll
        for (int k = 0; k < 8; k++)
            if (pos[k] >= 0) g_csr[pos[k]] = s[k];
    } else {
        for (int k = base; k < E; k++) {
            int rk = g_rank[k];
            if (rk >= 0) {
                int s = src[k], d = dst[k];
                if ((unsigned)s < (unsigned)n)
                    g_csr[g_roff[d] + 1 + rk] = s;
            }
        }
    }
}

__global__ void k_scatter64(const long long* __restrict__ src,
                            const long long* __restrict__ dst, int E, int n) {
    int e = blockIdx.x * blockDim.x + threadIdx.x;
    if (e >= E) return;
    int s = (int)src[e], d = (int)dst[e];
    if ((unsigned)s >= (unsigned)n || (unsigned)d >= (unsigned)n) return;
    int pos = atomicAdd(&g_cur[d], 1);
    g_csr[pos] = s;
}

// int64 fallback lin1 (separate, unfused)
__global__ void __launch_bounds__(256) k_lin1_only(
    const float* __restrict__ x,
    const float* __restrict__ Wc, const float* __restrict__ asc_, const float* __restrict__ adc,
    const float* __restrict__ Wr, const float* __restrict__ asr_, const float* __restrict__ adr,
    int n) {
    __shared__ float Wsc[64 * HID], Wsr[64 * HID];
    __shared__ float av[4 * HID];
    for (int i = threadIdx.x; i < 64 * HID; i += blockDim.x) {
        Wsc[i] = Wc[i]; Wsr[i] = Wr[i];
    }
    if (threadIdx.x < HID) {
        av[threadIdx.x]           = asc_[threadIdx.x];
        av[HID + threadIdx.x]     = adc[threadIdx.x];
        av[2 * HID + threadIdx.x] = asr_[threadIdx.x];
        av[3 * HID + threadIdx.x] = adr[threadIdx.x];
    }
    __syncthreads();
    int gw = (blockIdx.x * blockDim.x + threadIdx.x) >> 5;
    int lane = threadIdx.x & 31;
    if (gw >= n) return;
    const float* xr = x + (size_t)gw * 64;
    float ac = 0.f, ar = 0.f;
    #pragma unroll
    for (int k = 0; k < 64; k++) {
        float xv = xr[k];
        ac = fmaf(xv, Wsc[k * HID + lane], ac);
        ar = fmaf(xv, Wsr[k * HID + lane], ar);
    }
    g_lin[(size_t)gw * HID + lane] = __floats2half2_rn(ac, ar);
    float e0 = ac * av[lane], e1 = ac * av[HID + lane];
    float e2 = ar * av[2 * HID + lane], e3 = ar * av[3 * HID + lane];
    #pragma unroll
    for (int o = 16; o; o >>= 1) {
        e0 += __shfl_xor_sync(0xffffffffu, e0, o);
        e1 += __shfl_xor_sync(0xffffffffu, e1, o);
        e2 += __shfl_xor_sync(0xffffffffu, e2, o);
        e3 += __shfl_xor_sync(0xffffffffu, e3, o);
    }
    if (lane == 0) {
        g_es[gw] = make_float2(e0, e2);
        g_ed[gw] = make_float2(e1, e3);
    }
}

// ---------- core single-pass agg: FULL row per instruction ----------
// Layout: 4 sub-edges (eidx = lane>>3) x 8 chunks (cg = lane&7, 16B each).
// One LDG.128 covers 4 complete 128B rows -> 4 L1 wavefronts per 4 edges
// = 1 wavefront/edge (was 2). Lane cg owns channels cg*4..cg*4+3.
__device__ __forceinline__ void agg_core(const __half2* __restrict__ lin,
                                         const float2* __restrict__ es,
                                         const float2* __restrict__ edv,
                                         int gw, int lane,
                                         float* accc, float* accr,
                                         float& invc, float& invr) {
    int beg = g_roff[gw], end = g_roff[gw + 1];
    float2 ed = edv[gw];
    int eidx = lane >> 3;   // 0..3 sub-edge
    int cg   = lane & 7;    // 0..7 16B chunk (4 channels)
    float sc = 0.f, sr = 0.f;
    #pragma unroll
    for (int j = 0; j < 4; j++) { accc[j] = 0.f; accr[j] = 0.f; }

    // prefetch first chunk's csr
    int i0 = beg + lane;
    int s_next = (i0 < end) ? g_csr[i0] : 0;

    for (int base = beg; base < end; base += 32) {
        int s_l = s_next;
        float2 e = es[s_l];
        int inext = base + 32 + lane;
        int s_n2 = 0;
        if (inext < end) s_n2 = g_csr[inext];
        float wc = 0.f, wr = 0.f;
        if (base + lane < end) {
            float ac_ = e.x + ed.x; ac_ = (ac_ > 0.f) ? ac_ : 0.2f * ac_;
            float ar_ = e.y + ed.y; ar_ = (ar_ > 0.f) ? ar_ : 0.2f * ar_;
            wc = __expf(ac_); wr = __expf(ar_);
        }
        sc += wc; sr += wr;

        #pragma unroll
        for (int j = 0; j < 8; j++) {
            if (base + j * 4 >= end) break;             // warp-uniform
            int lsrc = j * 4 + eidx;
            float wcx = __shfl_sync(0xffffffffu, wc, lsrc);
            float wrx = __shfl_sync(0xffffffffu, wr, lsrc);
            int   s   = __shfl_sync(0xffffffffu, s_l, lsrc);
            const char* rowb = (const char*)(lin + (size_t)s * HID);
            const uint4 u = *(const uint4*)(rowb + cg * 16);   // ch cg*4..+3
            float2 f0 = __half22float2(*(const __half2*)&u.x);
            float2 f1 = __half22float2(*(const __half2*)&u.y);
            float2 f2 = __half22float2(*(const __half2*)&u.z);
            float2 f3 = __half22float2(*(const __half2*)&u.w);
            accc[0] = fmaf(wcx, f0.x, accc[0]); accr[0] = fmaf(wrx, f0.y, accr[0]);
            accc[1] = fmaf(wcx, f1.x, accc[1]); accr[1] = fmaf(wrx, f1.y, accr[1]);
            accc[2] = fmaf(wcx, f2.x, accc[2]); accr[2] = fmaf(wrx, f2.y, accr[2]);
            accc[3] = fmaf(wcx, f3.x, accc[3]); accr[3] = fmaf(wrx, f3.y, accr[3]);
        }
        s_next = s_n2;
    }
    #pragma unroll
    for (int o = 16; o; o >>= 1) {
        sc += __shfl_xor_sync(0xffffffffu, sc, o);
        sr += __shfl_xor_sync(0xffffffffu, sr, o);
    }
    invc = 1.0f / sc; invr = 1.0f / sr;
    // reduce across the 4 sub-edge groups (xor 8, 16)
    #pragma unroll
    for (int o = 8; o <= 16; o <<= 1) {
        #pragma unroll
        for (int j = 0; j < 4; j++) {
            accc[j] += __shfl_xor_sync(0xffffffffu, accc[j], o);
            accr[j] += __shfl_xor_sync(0xffffffffu, accr[j], o);
        }
    }
}

// channel-k ownership: channel k lives on lane k>>2, register k&3
#define CH_LANE(k)  ((k) >> 2)
#define CH_REG(k)   ((k) & 3)

// ---- aggA: layer-1 agg + ReLU + layer-2 linear + layer-2 att coeffs ----
__global__ void __launch_bounds__(256) k_aggA(
    const float* __restrict__ b1c, const float* __restrict__ b1r,
    const float* __restrict__ W2c, const float* __restrict__ as2c, const float* __restrict__ ad2c,
    const float* __restrict__ W2r, const float* __restrict__ as2r, const float* __restrict__ ad2r,
    int n) {
    __shared__ float Wsc[HID * HID], Wsr[HID * HID];
    __shared__ float bsh[2 * HID];
    __shared__ float av[4 * HID];
    for (int i = threadIdx.x; i < HID * HID; i += blockDim.x) {
        Wsc[i] = W2c[i]; Wsr[i] = W2r[i];
    }
    if (threadIdx.x < HID) {
        bsh[threadIdx.x]          = b1c[threadIdx.x];
        bsh[HID + threadIdx.x]    = b1r[threadIdx.x];
        av[threadIdx.x]           = as2c[threadIdx.x];
        av[HID + threadIdx.x]     = ad2c[threadIdx.x];
        av[2 * HID + threadIdx.x] = as2r[threadIdx.x];
        av[3 * HID + threadIdx.x] = ad2r[threadIdx.x];
    }
    __syncthreads();
    int gw = (blockIdx.x * blockDim.x + threadIdx.x) >> 5;
    int lane = threadIdx.x & 31;
    if (gw >= n) return;
    int cg = lane & 7;

    float accc[4], accr[4], invc, invr;
    agg_core(g_lin, g_es, g_ed, gw, lane, accc, accr, invc, invr);

    float hc[4], hr[4];
    #pragma unroll
    for (int j = 0; j < 4; j++) {
        int ch = cg * 4 + j;
        hc[j] = fmaxf(fmaf(accc[j], invc, bsh[ch]), 0.f);
        hr[j] = fmaxf(fmaf(accr[j], invr, bsh[HID + ch]), 0.f);
    }
    // layer-2 linear: channel k on lane k>>2, register k&3
    float ac = 0.f, ar = 0.f;
    #pragma unroll
    for (int k = 0; k < HID; k++) {
        float tc = __shfl_sync(0xffffffffu, hc[CH_REG(k)], CH_LANE(k));
        float tr = __shfl_sync(0xffffffffu, hr[CH_REG(k)], CH_LANE(k));
        ac = fmaf(tc, Wsc[k * HID + lane], ac);
        ar = fmaf(tr, Wsr[k * HID + lane], ar);
    }
    g_lin2[(size_t)gw * HID + lane] = __floats2half2_rn(ac, ar);
    float e0 = ac * av[lane], e1 = ac * av[HID + lane];
    float e2 = ar * av[2 * HID + lane], e3 = ar * av[3 * HID + lane];
    #pragma unroll
    for (int o = 16; o; o >>= 1) {
        e0 += __shfl_xor_sync(0xffffffffu, e0, o);
        e1 += __shfl_xor_sync(0xffffffffu, e1, o);
        e2 += __shfl_xor_sync(0xffffffffu, e2, o);
        e3 += __shfl_xor_sync(0xffffffffu, e3, o);
    }
    if (lane == 0) {
        g_es2[gw] = make_float2(e0, e2);
        g_ed2[gw] = make_float2(e1, e3);
    }
}

// ---- aggB: layer-2 agg + ReLU + head GEMMs + sigmoid(c) -> d_out ----
__global__ void __launch_bounds__(256) k_aggB(
    const float* __restrict__ b2c, const float* __restrict__ b2r,
    const float* __restrict__ lWc, const float* __restrict__ lbc,
    const float* __restrict__ lWr, const float* __restrict__ lbr,
    float* __restrict__ out, int n) {
    __shared__ float Wsc[HID * HID], Wsr[HID * HID];
    __shared__ float bsh[2 * HID];
    __shared__ float lbsh[2 * HID];
    for (int i = threadIdx.x; i < HID * HID; i += blockDim.x) {
        Wsc[i] = lWc[i]; Wsr[i] = lWr[i];
    }
    if (threadIdx.x < HID) {
        bsh[threadIdx.x]        = b2c[threadIdx.x];
        bsh[HID + threadIdx.x]  = b2r[threadIdx.x];
        lbsh[threadIdx.x]       = lbc[threadIdx.x];
        lbsh[HID + threadIdx.x] = lbr[threadIdx.x];
    }
    __syncthreads();
    int gw = (blockIdx.x * blockDim.x + threadIdx.x) >> 5;
    int lane = threadIdx.x & 31;
    if (gw >= n) return;
    int cg = lane & 7;

    float accc[4], accr[4], invc, invr;
    agg_core(g_lin2, g_es2, g_ed2, gw, lane, accc, accr, invc, invr);

    float hc[4], hr[4];
    #pragma unroll
    for (int j = 0; j < 4; j++) {
        int ch = cg * 4 + j;
        hc[j] = fmaxf(fmaf(accc[j], invc, bsh[ch]), 0.f);
        hr[j] = fmaxf(fmaf(accr[j], invr, bsh[HID + ch]), 0.f);
    }
    float ac = lbsh[lane], ar = lbsh[HID + lane];
    #pragma unroll
    for (int k = 0; k < HID; k++) {
        float tc = __shfl_sync(0xffffffffu, hc[CH_REG(k)], CH_LANE(k));
        float tr = __shfl_sync(0xffffffffu, hr[CH_REG(k)], CH_LANE(k));
        ac = fmaf(tc, Wsc[k * HID + lane], ac);
        ar = fmaf(tr, Wsr[k * HID + lane], ar);
    }
    out[(size_t)gw * HID + lane] = 1.0f / (1.0f + __expf(-ac));
    out[(size_t)n * HID + (size_t)gw * HID + lane] = ar;
}

// ---------------- launch ----------------
extern "C" void kernel_launch(void* const* d_in, const int* in_sizes, int n_in,
                              void* d_out, int out_size) {
    const float* x = (const float*)d_in[0];
    int n = in_sizes[0] / 64;

    // params: c at d_in[2..11], r at d_in[12..21]
    const float** c = (const float**)(d_in + 2);
    const float** r = (const float**)(d_in + 12);

    const int T = 256;
    long long nelem = in_sizes[1];
    int nb_scan = (n + 1023) / 1024;
    int nb = (n * 32 + T - 1) / T;  // warp per node

    if (nelem == 2LL * EEMAX) {            // int32 [2, E]
        const int* ei = (const int*)d_in[1];
        int E = EEMAX;
        int nt8 = (E + 7) / 8;
        int nb_hist = (nt8 + T - 1) / T;
        k_front<<<nb + nb_hist, T>>>(x, c[0], c[1], c[2], r[0], r[1], r[2],
                                     ei + E, E, n, nb);
        kb_scan_lb<<<nb_scan, 1024>>>(nb_scan, n);
        k_scatter8<<<nb_hist, T>>>(ei, ei + E, E, n);
    } else {                               // int64 [2, E] fallback
        const long long* ei = (const long long*)d_in[1];
        int E = (int)(nelem / 2);
        k_lin1_only<<<nb, T>>>(x, c[0], c[1], c[2], r[0], r[1], r[2], n);
        k_hist64<<<(E + T - 1) / T, T>>>(ei + E, E, n);
        kb_scan_lb<<<nb_scan, 1024>>>(nb_scan, n);
        k_scatter64<<<(E + T - 1) / T, T>>>(ei, ei + E, E, n);
    }

    k_aggA<<<nb, T>>>(c[3], r[3], c[4], c[5], c[6], r[4], r[5], r[6], n);
    k_aggB<<<nb, T>>>(c[7], r[7], c[8], c[9], r[8], r[9], (float*)d_out, n);
}